// round 5
// baseline (speedup 1.0000x reference)
#include <cuda_runtime.h>
#include <math.h>

// ---------------------------------------------------------------------------
// Problem constants: B=32, S=T=64, E=H=512, G=3H=1536, V=32000
// ---------------------------------------------------------------------------

// Scratch offsets (in floats) into one big __device__ buffer
#define OF_ESRC 0ul            /* 2048*512  */
#define OF_ETGT 1048576ul      /* 2048*512  */
#define OF_GXF  2097152ul      /* 2048*1536 */
#define OF_GXB  5242880ul      /* 2048*1536 */
#define OF_DGX  8388608ul      /* 2048*1536 */
#define OF_SRCH 11534336ul     /* 2048*1024 */
#define OF_UH   13631488ul     /* 2048*512  */
#define OF_DOUT 14680064ul     /* 2048*512  */
#define OF_HF   15728640ul     /* 2*32*512 double buffer */
#define OF_HB   15761408ul     /* 2*32*512 */
#define OF_HD   15794176ul     /* 2*32*512 */
#define OF_CTX  15826944ul     /* 32*1024 */
#define OF_PART 15859712ul     /* 6*32*1536 dec split-K partials */
#define OF_LP   16154624ul     /* 2048*500*2 logits (max,sumexp) partials */
#define OF_CON  18202624ul     /* 2048 */
#define OF_CNT  18204672ul     /* 2048 */
#define BUF_TOTAL 18206720ul

__device__ __align__(16) float g_buf[BUF_TOTAL];

__device__ __forceinline__ float sigm(float x) { return 1.f / (1.f + __expf(-x)); }
__device__ __forceinline__ float dot4(float4 a, float4 b, float acc) {
    acc = fmaf(a.x, b.x, acc); acc = fmaf(a.y, b.y, acc);
    acc = fmaf(a.z, b.z, acc); acc = fmaf(a.w, b.w, acc);
    return acc;
}

// ---------------------------------------------------------------------------
// zero initial hidden states (runs every replay)
// ---------------------------------------------------------------------------
__global__ void k_zero() {
    int i = blockIdx.x * 256 + threadIdx.x;   // grid 64 -> 16384
    g_buf[OF_HF + i] = 0.f;
    g_buf[OF_HB + i] = 0.f;
    g_buf[OF_HD + i] = 0.f;
}

// ---------------------------------------------------------------------------
// embedding gather: row r -> table[ids[r]] (512 floats)
// ---------------------------------------------------------------------------
__global__ void k_embed(const int* __restrict__ ids, const float* __restrict__ tab,
                        size_t out_off) {
    int row = blockIdx.x;
    const float4* src = (const float4*)(tab + (size_t)ids[row] * 512);
    float4* dst = (float4*)(g_buf + out_off + (size_t)row * 512);
    dst[threadIdx.x] = src[threadIdx.x];
}

// ---------------------------------------------------------------------------
// Generic GEMM: C[M,N] = A[M,K] @ W[N,K]^T + bias
// BM=64, BN=64, BK=16, 128 threads, 8x4 microtile. A and C live in g_buf.
// ---------------------------------------------------------------------------
__global__ __launch_bounds__(128) void k_gemm(
    size_t a_off, int lda, const float* __restrict__ W, int ldw,
    const float* __restrict__ bias, size_t c_off, int ldc, int K)
{
    const float* A = g_buf + a_off;
    float* C = g_buf + c_off;
    __shared__ float As[16][68];
    __shared__ float Ws[16][68];
    int bm = blockIdx.y * 64, bn = blockIdx.x * 64;
    int t = threadIdx.x;
    int tm = t >> 4, tn = t & 15;
    int lr = t >> 1, lk = (t & 1) * 8;
    float acc[8][4] = {};

    for (int k0 = 0; k0 < K; k0 += 16) {
        float4 a0 = *(const float4*)(A + (size_t)(bm + lr) * lda + k0 + lk);
        float4 a1 = *(const float4*)(A + (size_t)(bm + lr) * lda + k0 + lk + 4);
        As[lk+0][lr]=a0.x; As[lk+1][lr]=a0.y; As[lk+2][lr]=a0.z; As[lk+3][lr]=a0.w;
        As[lk+4][lr]=a1.x; As[lk+5][lr]=a1.y; As[lk+6][lr]=a1.z; As[lk+7][lr]=a1.w;
        float4 w0 = *(const float4*)(W + (size_t)(bn + lr) * ldw + k0 + lk);
        float4 w1 = *(const float4*)(W + (size_t)(bn + lr) * ldw + k0 + lk + 4);
        Ws[lk+0][lr]=w0.x; Ws[lk+1][lr]=w0.y; Ws[lk+2][lr]=w0.z; Ws[lk+3][lr]=w0.w;
        Ws[lk+4][lr]=w1.x; Ws[lk+5][lr]=w1.y; Ws[lk+6][lr]=w1.z; Ws[lk+7][lr]=w1.w;
        __syncthreads();
#pragma unroll
        for (int k = 0; k < 16; k++) {
            float4 x0 = *(const float4*)&As[k][tm*8];
            float4 x1 = *(const float4*)&As[k][tm*8+4];
            float4 y  = *(const float4*)&Ws[k][tn*4];
            float xa[8] = {x0.x,x0.y,x0.z,x0.w,x1.x,x1.y,x1.z,x1.w};
            float yb[4] = {y.x,y.y,y.z,y.w};
#pragma unroll
            for (int i = 0; i < 8; i++)
#pragma unroll
                for (int j = 0; j < 4; j++)
                    acc[i][j] = fmaf(xa[i], yb[j], acc[i][j]);
        }
        __syncthreads();
    }
    float4 bv = *(const float4*)(bias + bn + tn*4);
#pragma unroll
    for (int i = 0; i < 8; i++) {
        float4 o = make_float4(acc[i][0]+bv.x, acc[i][1]+bv.y,
                               acc[i][2]+bv.z, acc[i][3]+bv.w);
        *(float4*)(C + (size_t)(bm + tm*8 + i) * ldc + bn + tn*4) = o;
    }
}

// ---------------------------------------------------------------------------
// Encoder step: fused gh = h @ Whh^T, GRU cell, mask, write src_hidden.
// Grid 128 = dir(2) x colgroup(64, 8 h-cols each). 128 threads.
// h is double-buffered (pin = step parity).
// ---------------------------------------------------------------------------
__global__ __launch_bounds__(128) void k_enc_step(
    int s, const float* __restrict__ Whh_f, const float* __restrict__ bhh_f,
    const float* __restrict__ Whh_b, const float* __restrict__ bhh_b,
    const int* __restrict__ slen, int pin)
{
    int dir = blockIdx.x >> 6;
    int j0 = (blockIdx.x & 63) * 8;
    const float* Whh = dir ? Whh_b : Whh_f;
    const float* bhh = dir ? bhh_b : bhh_f;
    size_t hb = dir ? OF_HB : OF_HF;
    const float* hin = g_buf + hb + (size_t)pin * 16384;
    float* hout = g_buf + hb + (size_t)(pin ^ 1) * 16384;
    const float* gx = g_buf + (dir ? OF_GXB : OF_GXF);
    int tt = dir ? (63 - s) : s;

    __shared__ float Hs[32][68];
    __shared__ float Ws[24][68];
    int t = threadIdx.x;
    int rp = t >> 3;          // 0..15 -> rows rp, rp+16
    int j  = t & 7;
    float ar[2] = {0.f,0.f}, az[2] = {0.f,0.f}, an[2] = {0.f,0.f};
    int lrow = t >> 2, lkv = (t & 3) * 4;

    for (int k0 = 0; k0 < 512; k0 += 64) {
#pragma unroll
        for (int i = 0; i < 4; i++) {
            int kv = lkv + i;
            *(float4*)&Hs[lrow][kv*4] =
                *(const float4*)(hin + (size_t)lrow*512 + k0 + kv*4);
        }
#pragma unroll
        for (int i = 0; i < 3; i++) {
            int lin = t + 128*i;          // 0..383
            int wr = lin >> 4, kv = lin & 15;
            int g = wr >> 3, jj = wr & 7;
            *(float4*)&Ws[wr][kv*4] =
                *(const float4*)(Whh + (size_t)(g*512 + j0 + jj)*512 + k0 + kv*4);
        }
        __syncthreads();
#pragma unroll
        for (int kv = 0; kv < 16; kv++) {
            float4 h0 = *(const float4*)&Hs[rp][kv*4];
            float4 h1 = *(const float4*)&Hs[rp+16][kv*4];
            float4 wrv = *(const float4*)&Ws[j][kv*4];
            float4 wzv = *(const float4*)&Ws[8+j][kv*4];
            float4 wnv = *(const float4*)&Ws[16+j][kv*4];
            ar[0] = dot4(h0, wrv, ar[0]); ar[1] = dot4(h1, wrv, ar[1]);
            az[0] = dot4(h0, wzv, az[0]); az[1] = dot4(h1, wzv, az[1]);
            an[0] = dot4(h0, wnv, an[0]); an[1] = dot4(h1, wnv, an[1]);
        }
        __syncthreads();
    }
    int jg = j0 + j;
    float br = bhh[jg], bz = bhh[512+jg], bn = bhh[1024+jg];
#pragma unroll
    for (int q = 0; q < 2; q++) {
        int r = rp + q*16;                 // batch index
        size_t grow = (size_t)r*64 + tt;
        float gxr = gx[grow*1536 + jg];
        float gxz = gx[grow*1536 + 512 + jg];
        float gxn = gx[grow*1536 + 1024 + jg];
        float rr = sigm(gxr + ar[q] + br);
        float zz = sigm(gxz + az[q] + bz);
        float nn = tanhf(gxn + rr * (an[q] + bn));
        float hold = hin[(size_t)r*512 + jg];
        float hnew = (1.f - zz) * nn + zz * hold;
        bool m = tt < slen[r];
        hout[(size_t)r*512 + jg] = m ? hnew : hold;
        g_buf[OF_SRCH + grow*1024 + (size_t)dir*512 + jg] = m ? hnew : 0.f;
    }
}

// ---------------------------------------------------------------------------
// Decoder attention (one block per batch row): q = A_W@h + A_b;
// e[s] = A_v . tanh(Uh[b,s] + q) + knockout; alpha = softmax; ctx = alpha.H
// ---------------------------------------------------------------------------
__global__ __launch_bounds__(256) void k_attn(
    const float* __restrict__ A_W, const float* __restrict__ A_b,
    const float* __restrict__ A_v, const int* __restrict__ slen, int pin)
{
    int b = blockIdx.x;
    int t = threadIdx.x;
    __shared__ float hs[512], qs[512], av[512], es[64];
    const float* hin = g_buf + OF_HD + (size_t)pin*16384 + (size_t)b*512;
    hs[t] = hin[t]; hs[t+256] = hin[t+256];
    av[t] = A_v[t]; av[t+256] = A_v[t+256];
    __syncthreads();
#pragma unroll
    for (int jj = 0; jj < 2; jj++) {
        int jq = t + jj*256;
        const float* wrow = A_W + (size_t)jq*512;
        float acc = A_b[jq];
        for (int k = 0; k < 512; k += 4)
            acc = dot4(*(const float4*)(wrow + k), *(const float4*)&hs[k], acc);
        qs[jq] = acc;
    }
    __syncthreads();
    int w = t >> 5, lane = t & 31;
    int sl = slen[b];
#pragma unroll
    for (int si = 0; si < 8; si++) {
        int s = w*8 + si;
        const float* uh = g_buf + OF_UH + ((size_t)b*64 + s)*512;
        float acc = 0.f;
        for (int jq = lane; jq < 512; jq += 32)
            acc = fmaf(av[jq], tanhf(uh[jq] + qs[jq]), acc);
#pragma unroll
        for (int o = 16; o > 0; o >>= 1) acc += __shfl_xor_sync(0xffffffffu, acc, o);
        if (lane == 0) es[s] = (s < sl) ? acc : acc - 1e9f;
    }
    __syncthreads();
    if (t < 32) {
        float a0 = es[t], a1 = es[t+32];
        float m = fmaxf(a0, a1);
#pragma unroll
        for (int o = 16; o > 0; o >>= 1) m = fmaxf(m, __shfl_xor_sync(0xffffffffu, m, o));
        float e0 = __expf(a0 - m), e1 = __expf(a1 - m);
        float sum = e0 + e1;
#pragma unroll
        for (int o = 16; o > 0; o >>= 1) sum += __shfl_xor_sync(0xffffffffu, sum, o);
        es[t] = e0 / sum; es[t+32] = e1 / sum;
    }
    __syncthreads();
#pragma unroll
    for (int dd = 0; dd < 4; dd++) {
        int d = t + dd*256;
        const float* sh = g_buf + OF_SRCH + (size_t)b*64*1024 + d;
        float acc = 0.f;
        for (int s = 0; s < 64; s++)
            acc = fmaf(es[s], sh[(size_t)s*1024], acc);
        g_buf[OF_CTX + (size_t)b*1024 + d] = acc;
    }
}

// ---------------------------------------------------------------------------
// Decoder gate GEMM (split-K): gh = [ctx ; h] @ [Wih[:,512:] ; Whh]^T
// grid (24 colblocks x 6 kchunks of 256), 256 threads.
// Warp-broadcast microtile: lane=row(32), each warp 8 gate-cols.
// Writes partials part[kc][32][1536].
// ---------------------------------------------------------------------------
__global__ __launch_bounds__(256) void k_dec_gemm(
    const float* __restrict__ Wih, const float* __restrict__ Whh, int pin)
{
    int n0 = blockIdx.x * 64;
    int kc = blockIdx.y;
    const float* A; int lda; const float* W; int ldw; int woff; int kbase;
    if (kc < 4) { A = g_buf + OF_CTX; lda = 1024; W = Wih; ldw = 1536; woff = 512; kbase = kc*256; }
    else { A = g_buf + OF_HD + (size_t)pin*16384; lda = 512; W = Whh; ldw = 512; woff = 0; kbase = (kc-4)*256; }

    __shared__ float Hs[64][33];
    __shared__ float Ws2[64][68];
    int t = threadIdx.x;
    int w = t >> 5, lane = t & 31;
    float acc[8] = {};

    for (int k0 = 0; k0 < 256; k0 += 64) {
#pragma unroll
        for (int i = 0; i < 2; i++) {
            int vec = t + 256*i;           // 0..511
            int r = vec >> 4, kv = vec & 15;
            float4 a = *(const float4*)(A + (size_t)r*lda + kbase + k0 + kv*4);
            Hs[kv*4+0][r]=a.x; Hs[kv*4+1][r]=a.y; Hs[kv*4+2][r]=a.z; Hs[kv*4+3][r]=a.w;
        }
#pragma unroll
        for (int i = 0; i < 4; i++) {
            int vec = t + 256*i;           // 0..1023
            int nl = vec >> 4, kv = vec & 15;
            float4 wv = *(const float4*)(W + (size_t)(n0+nl)*ldw + woff + kbase + k0 + kv*4);
            Ws2[kv*4+0][nl]=wv.x; Ws2[kv*4+1][nl]=wv.y; Ws2[kv*4+2][nl]=wv.z; Ws2[kv*4+3][nl]=wv.w;
        }
        __syncthreads();
#pragma unroll
        for (int k = 0; k < 64; k++) {
            float hv = Hs[k][lane];
            float4 w0 = *(const float4*)&Ws2[k][w*8];
            float4 w1 = *(const float4*)&Ws2[k][w*8+4];
            acc[0]=fmaf(hv,w0.x,acc[0]); acc[1]=fmaf(hv,w0.y,acc[1]);
            acc[2]=fmaf(hv,w0.z,acc[2]); acc[3]=fmaf(hv,w0.w,acc[3]);
            acc[4]=fmaf(hv,w1.x,acc[4]); acc[5]=fmaf(hv,w1.y,acc[5]);
            acc[6]=fmaf(hv,w1.z,acc[6]); acc[7]=fmaf(hv,w1.w,acc[7]);
        }
        __syncthreads();
    }
    float* part = g_buf + OF_PART + (size_t)kc*49152 + (size_t)lane*1536 + n0 + w*8;
#pragma unroll
    for (int c = 0; c < 8; c++) part[c] = acc[c];
}

// ---------------------------------------------------------------------------
// Decoder pointwise GRU: combine split-K partials + dgx, update h, write dec_out
// ---------------------------------------------------------------------------
__global__ void k_dec_point(int i, const float* __restrict__ bhh,
                            const int* __restrict__ tlen, int pin)
{
    int b = blockIdx.x;
    int j = threadIdx.x;          // 512
    float gr = 0.f, gz = 0.f, gn = 0.f;
#pragma unroll
    for (int kc = 0; kc < 6; kc++) {
        const float* p = g_buf + OF_PART + (size_t)kc*49152 + (size_t)b*1536;
        gr += p[j]; gz += p[512+j]; gn += p[1024+j];
    }
    const float* hin = g_buf + OF_HD + (size_t)pin*16384;
    float* hout = g_buf + OF_HD + (size_t)(pin^1)*16384;
    size_t grow = (size_t)b*64 + i;
    const float* gx = g_buf + OF_DGX + grow*1536;
    float rr = sigm(gx[j] + gr + bhh[j]);
    float zz = sigm(gx[512+j] + gz + bhh[512+j]);
    float nn = tanhf(gx[1024+j] + rr*(gn + bhh[1024+j]));
    float hold = hin[(size_t)b*512 + j];
    float hnew = (1.f - zz)*nn + zz*hold;
    bool m = i < tlen[b];
    hout[(size_t)b*512 + j] = m ? hnew : hold;
    g_buf[OF_DOUT + grow*512 + j] = m ? hnew : 0.f;
}

// ---------------------------------------------------------------------------
// Logits GEMM with fused per-row (max, sumexp) partial log-softmax.
// Grid (500, 32): 64 rows x 64 vocab cols per block. Never writes logits.
// ---------------------------------------------------------------------------
__global__ __launch_bounds__(128) void k_logits(
    const float* __restrict__ W, const float* __restrict__ bias)
{
    __shared__ float As[16][68];
    __shared__ float Ws[16][68];
    __shared__ float red[64][17];
    __shared__ float rowm[64];
    const float* A = g_buf + OF_DOUT;
    int bm = blockIdx.y * 64, bn = blockIdx.x * 64;
    int t = threadIdx.x, tm = t >> 4, tn = t & 15;
    int lr = t >> 1, lk = (t & 1) * 8;
    float acc[8][4] = {};

    for (int k0 = 0; k0 < 512; k0 += 16) {
        float4 a0 = *(const float4*)(A + (size_t)(bm + lr)*512 + k0 + lk);
        float4 a1 = *(const float4*)(A + (size_t)(bm + lr)*512 + k0 + lk + 4);
        As[lk+0][lr]=a0.x; As[lk+1][lr]=a0.y; As[lk+2][lr]=a0.z; As[lk+3][lr]=a0.w;
        As[lk+4][lr]=a1.x; As[lk+5][lr]=a1.y; As[lk+6][lr]=a1.z; As[lk+7][lr]=a1.w;
        float4 w0 = *(const float4*)(W + (size_t)(bn + lr)*512 + k0 + lk);
        float4 w1 = *(const float4*)(W + (size_t)(bn + lr)*512 + k0 + lk + 4);
        Ws[lk+0][lr]=w0.x; Ws[lk+1][lr]=w0.y; Ws[lk+2][lr]=w0.z; Ws[lk+3][lr]=w0.w;
        Ws[lk+4][lr]=w1.x; Ws[lk+5][lr]=w1.y; Ws[lk+6][lr]=w1.z; Ws[lk+7][lr]=w1.w;
        __syncthreads();
#pragma unroll
        for (int k = 0; k < 16; k++) {
            float4 x0 = *(const float4*)&As[k][tm*8];
            float4 x1 = *(const float4*)&As[k][tm*8+4];
            float4 y  = *(const float4*)&Ws[k][tn*4];
            float xa[8] = {x0.x,x0.y,x0.z,x0.w,x1.x,x1.y,x1.z,x1.w};
            float yb[4] = {y.x,y.y,y.z,y.w};
#pragma unroll
            for (int i = 0; i < 8; i++)
#pragma unroll
                for (int j = 0; j < 4; j++)
                    acc[i][j] = fmaf(xa[i], yb[j], acc[i][j]);
        }
        __syncthreads();
    }
    float4 bv = *(const float4*)(bias + bn + tn*4);
#pragma unroll
    for (int i = 0; i < 8; i++) {
        acc[i][0]+=bv.x; acc[i][1]+=bv.y; acc[i][2]+=bv.z; acc[i][3]+=bv.w;
        red[tm*8+i][tn] = fmaxf(fmaxf(acc[i][0],acc[i][1]), fmaxf(acc[i][2],acc[i][3]));
    }
    __syncthreads();
    if (t < 64) {
        float m = red[t][0];
#pragma unroll
        for (int c = 1; c < 16; c++) m = fmaxf(m, red[t][c]);
        rowm[t] = m;
    }
    __syncthreads();
#pragma unroll
    for (int i = 0; i < 8; i++) {
        float m = rowm[tm*8+i];
        red[tm*8+i][tn] = __expf(acc[i][0]-m) + __expf(acc[i][1]-m)
                        + __expf(acc[i][2]-m) + __expf(acc[i][3]-m);
    }
    __syncthreads();
    if (t < 64) {
        float l = 0.f;
#pragma unroll
        for (int c = 0; c < 16; c++) l += red[t][c];
        size_t row = bm + t;
        g_buf[OF_LP + row*1000 + (size_t)blockIdx.x*2] = rowm[t];
        g_buf[OF_LP + row*1000 + (size_t)blockIdx.x*2 + 1] = l;
    }
}

// ---------------------------------------------------------------------------
// Per-row: combine 500 (m,l) partials -> logZ; picked logit via dot; contrib
// One warp per row; grid 256 x 256 threads.
// ---------------------------------------------------------------------------
__global__ __launch_bounds__(256) void k_combine(
    const int* __restrict__ tgt, const float* __restrict__ out_w,
    const float* __restrict__ out_b)
{
    int row = blockIdx.x * 8 + (threadIdx.x >> 5);
    int lane = threadIdx.x & 31;
    const float* p = g_buf + OF_LP + (size_t)row*1000;
    float M = -1e30f;
    for (int c = lane; c < 500; c += 32) M = fmaxf(M, p[c*2]);
#pragma unroll
    for (int o = 16; o > 0; o >>= 1) M = fmaxf(M, __shfl_xor_sync(0xffffffffu, M, o));
    float L = 0.f;
    for (int c = lane; c < 500; c += 32) L += p[c*2+1] * __expf(p[c*2] - M);
#pragma unroll
    for (int o = 16; o > 0; o >>= 1) L += __shfl_xor_sync(0xffffffffu, L, o);
    int b = row >> 6, tc = row & 63;
    int goal = (tc < 63) ? tgt[b*64 + tc + 1] : 0;
    float contrib = 0.f, cnt = 0.f;
    if (goal != 0) {
        const float* x = g_buf + OF_DOUT + (size_t)row*512;
        const float* wrow = out_w + (size_t)goal*512;
        float d = 0.f;
        for (int k = lane; k < 512; k += 32) d = fmaf(x[k], wrow[k], d);
#pragma unroll
        for (int o = 16; o > 0; o >>= 1) d += __shfl_xor_sync(0xffffffffu, d, o);
        contrib = (d + out_b[goal]) - (M + logf(L));
        cnt = 1.f;
    }
    if (lane == 0) {
        g_buf[OF_CON + row] = contrib;
        g_buf[OF_CNT + row] = cnt;
    }
}

// ---------------------------------------------------------------------------
// Final deterministic reduce -> loss
// ---------------------------------------------------------------------------
__global__ void k_final(float* out) {
    __shared__ float sc[1024], sn[1024];
    int t = threadIdx.x;
    sc[t] = g_buf[OF_CON + t] + g_buf[OF_CON + 1024 + t];
    sn[t] = g_buf[OF_CNT + t] + g_buf[OF_CNT + 1024 + t];
    __syncthreads();
    for (int o = 512; o > 0; o >>= 1) {
        if (t < o) { sc[t] += sc[t+o]; sn[t] += sn[t+o]; }
        __syncthreads();
    }
    if (t == 0) out[0] = -sc[0] / sn[0];
}

// ---------------------------------------------------------------------------
// Host orchestration (graph-capturable: kernel launches only, default stream)
// ---------------------------------------------------------------------------
extern "C" void kernel_launch(void* const* d_in, const int* in_sizes, int n_in,
                              void* d_out, int out_size)
{
    const int*   src_seqs = (const int*)  d_in[0];
    const int*   src_len  = (const int*)  d_in[1];
    const int*   tgt_seqs = (const int*)  d_in[2];
    const int*   tgt_len  = (const int*)  d_in[3];
    const float* src_emb  = (const float*)d_in[4];
    const float* eWih_f   = (const float*)d_in[5];
    const float* eWhh_f   = (const float*)d_in[6];
    const float* ebih_f   = (const float*)d_in[7];
    const float* ebhh_f   = (const float*)d_in[8];
    const float* eWih_b   = (const float*)d_in[9];
    const float* eWhh_b   = (const float*)d_in[10];
    const float* ebih_b   = (const float*)d_in[11];
    const float* ebhh_b   = (const float*)d_in[12];
    const float* tgt_emb  = (const float*)d_in[13];
    const float* dWih     = (const float*)d_in[14];
    const float* dWhh     = (const float*)d_in[15];
    const float* dbih     = (const float*)d_in[16];
    const float* dbhh     = (const float*)d_in[17];
    const float* U_w      = (const float*)d_in[18];
    const float* U_b      = (const float*)d_in[19];
    const float* A_W      = (const float*)d_in[20];
    const float* A_b      = (const float*)d_in[21];
    const float* A_v      = (const float*)d_in[22];
    const float* out_w    = (const float*)d_in[23];
    const float* out_b    = (const float*)d_in[24];

    k_zero<<<64, 256>>>();
    k_embed<<<2048, 128>>>(src_seqs, src_emb, OF_ESRC);
    k_embed<<<2048, 128>>>(tgt_seqs, tgt_emb, OF_ETGT);

    // input-gate pre-GEMMs (bias = bih folded in)
    k_gemm<<<dim3(24, 32), 128>>>(OF_ESRC, 512, eWih_f, 512, ebih_f, OF_GXF, 1536, 512);
    k_gemm<<<dim3(24, 32), 128>>>(OF_ESRC, 512, eWih_b, 512, ebih_b, OF_GXB, 1536, 512);
    k_gemm<<<dim3(24, 32), 128>>>(OF_ETGT, 512, dWih, 1536, dbih, OF_DGX, 1536, 512);

    for (int s = 0; s < 64; s++)
        k_enc_step<<<128, 128>>>(s, eWhh_f, ebhh_f, eWhh_b, ebhh_b, src_len, s & 1);

    k_gemm<<<dim3(8, 32), 128>>>(OF_SRCH, 1024, U_w, 1024, U_b, OF_UH, 512, 1024);

    for (int i = 0; i < 64; i++) {
        k_attn<<<32, 256>>>(A_W, A_b, A_v, src_len, i & 1);
        k_dec_gemm<<<dim3(24, 6), 256>>>(dWih, dWhh, i & 1);
        k_dec_point<<<32, 512>>>(i, dbhh, tgt_len, i & 1);
    }

    k_logits<<<dim3(500, 32), 128>>>(out_w, out_b);
    k_combine<<<256, 256>>>(tgt_seqs, out_w, out_b);
    k_final<<<1, 1024>>>((float*)d_out);
}